// round 13
// baseline (speedup 1.0000x reference)
#include <cuda_runtime.h>
#include <cuda_bf16.h>
#include <cstdint>

typedef unsigned long long ull;

// ---------------- problem constants ----------------
#define CIN   256
#define TT    64
#define HIN   32
#define WIN   32
#define C1    512
#define C2    512
#define NANCH 512

// conv1 GEMM: K1 = 27 taps * 256 ic (tap-major: k = tap*256 + ic)
#define K1      6912
#define NCHUNK1 324            // 3 segments * 108 (27 tap * 4 icc)
#define STAGE1_BYTES 40960     // A 8KB + B 32KB
#define C1MMA_SMEM  (2 * STAGE1_BYTES)   // 80KB, 2 CTAs/SM

// conv2 GEMM: K2 = 27 taps * 512 ic (tap-major), K-split x2, t-paired M=128
#define K2      13824
#define NCHUNK2H 324           // per K-half (chunks of 64)
#define STAGE2_BYTES 32768     // A 16KB + B 16KB
#define C2MMA_SMEM  (3 * STAGE2_BYTES)   // 96KB, 2 CTAs/SM

// padded activation tensors (ic innermost)
#define P1_ELEMS ((size_t)66 * 34 * 34 * 256)
#define P2_ELEMS ((size_t)66 * 18 * 18 * 512)

// ---------------- device scratch ----------------
__device__ __align__(16) __nv_bfloat16 g_p1h[P1_ELEMS];          // 39 MB
__device__ __align__(16) __nv_bfloat16 g_p1l[P1_ELEMS];          // 39 MB
__device__ __align__(16) __nv_bfloat16 g_p2h[P2_ELEMS];          // 22 MB
__device__ __align__(16) __nv_bfloat16 g_p2l[P2_ELEMS];          // 22 MB
__device__ __align__(16) __nv_bfloat16 g_b1h[(size_t)C1 * K1];   //  7 MB
__device__ __align__(16) __nv_bfloat16 g_b1l[(size_t)C1 * K1];   //  7 MB
__device__ __align__(16) __nv_bfloat16 g_b2h[(size_t)C2 * K2];   // 14 MB
__device__ __align__(16) __nv_bfloat16 g_b2l[(size_t)C2 * K2];   // 14 MB
__device__ float g_part[(size_t)2 * 64 * 64 * 512];              // 16.8 MB
__device__ float g_feat[C2 * TT];

// ---------------- helpers ----------------
__device__ __forceinline__ void cp16u(unsigned dst, const void* src) {
    asm volatile("cp.async.cg.shared.global [%0], [%1], 16;" :: "r"(dst), "l"(src));
}
__device__ __forceinline__ uint32_t smem_u32(const void* p) {
    return (uint32_t)__cvta_generic_to_shared(p);
}
__device__ __forceinline__ unsigned pack_bf2(float a, float b) {
    __nv_bfloat162 p = __floats2bfloat162_rn(a, b);
    return *reinterpret_cast<unsigned*>(&p);
}

// ============================================================================
// memzero (halo init for P1/P2)
// ============================================================================
__global__ void memzero(uint4* p, size_t n) {
    size_t i = (size_t)blockIdx.x * blockDim.x + threadIdx.x;
    size_t stride = (size_t)gridDim.x * blockDim.x;
    uint4 z = make_uint4(0u, 0u, 0u, 0u);
    for (; i < n; i += stride) p[i] = z;
}

// ============================================================================
// split_w1: w1[oc][ic*27+tap] -> b1 [oc][tap*256+ic] hi/lo
// ============================================================================
__global__ void split_w1(const float* __restrict__ w) {
    int oc = blockIdx.x;
    const float* src = w + (size_t)oc * K1;
    __nv_bfloat16* dh = g_b1h + (size_t)oc * K1;
    __nv_bfloat16* dl = g_b1l + (size_t)oc * K1;
#pragma unroll 3
    for (int j = 0; j < 27; j++) {
        int k = threadIdx.x + j * 256;
        int tap = k >> 8, ic = k & 255;
        float v = src[ic * 27 + tap];
        __nv_bfloat16 hi = __float2bfloat16(v);
        dh[k] = hi;
        dl[k] = __float2bfloat16(v - __bfloat162float(hi));
    }
}

// ============================================================================
// split_w2: w2[oc][ic*27+tap] -> b2 [oc][tap*512+ic] hi/lo
// ============================================================================
__global__ void split_w2(const float* __restrict__ w) {
    int oc = blockIdx.x;
    const float* src = w + (size_t)oc * (512 * 27);
    __nv_bfloat16* dh = g_b2h + (size_t)oc * K2;
    __nv_bfloat16* dl = g_b2l + (size_t)oc * K2;
#pragma unroll 6
    for (int j = 0; j < 54; j++) {
        int k = threadIdx.x + j * 256;
        int tap = k >> 9, ic = k & 511;
        float v = src[ic * 27 + tap];
        __nv_bfloat16 hi = __float2bfloat16(v);
        dh[k] = hi;
        dl[k] = __float2bfloat16(v - __bfloat162float(hi));
    }
}

// ============================================================================
// pad_split1: input [ic][t][h][w] fp32 -> P1 [t+1][h+1][w+1][ic] hi/lo bf16
// ============================================================================
__global__ void __launch_bounds__(256)
pad_split1(const float* __restrict__ in) {
    __shared__ float sm[256 * 33];
    const int t = blockIdx.x;
    const int h = blockIdx.y;
    const int tid = threadIdx.x;

#pragma unroll 8
    for (int j = 0; j < 32; j++) {
        int k = tid + j * 256;
        int ic = k >> 5, w = k & 31;
        sm[ic * 33 + w] = in[((size_t)(ic * TT + t) * HIN + h) * WIN + w];
    }
    __syncthreads();

    const int w   = tid >> 3;
    const int icg = tid & 7;
    float v[32];
#pragma unroll
    for (int i = 0; i < 32; i++) {
        int jj = i ^ (icg << 2);
        v[jj] = sm[(icg * 32 + jj) * 33 + w];
    }
    unsigned uh[16], ul[16];
#pragma unroll
    for (int p = 0; p < 16; p++) {
        float a = v[2 * p], b = v[2 * p + 1];
        uh[p] = pack_bf2(a, b);
        float ah = __bfloat162float(__float2bfloat16(a));
        float bh = __bfloat162float(__float2bfloat16(b));
        ul[p] = pack_bf2(a - ah, b - bh);
    }
    const size_t row = (((size_t)(t + 1) * 34) + (h + 1)) * 34 + (w + 1);
    uint4* dh = (uint4*)(g_p1h + row * 256 + icg * 32);
    uint4* dl = (uint4*)(g_p1l + row * 256 + icg * 32);
    dh[0] = make_uint4(uh[0], uh[1], uh[2], uh[3]);
    dh[1] = make_uint4(uh[4], uh[5], uh[6], uh[7]);
    dh[2] = make_uint4(uh[8], uh[9], uh[10], uh[11]);
    dh[3] = make_uint4(uh[12], uh[13], uh[14], uh[15]);
    dl[0] = make_uint4(ul[0], ul[1], ul[2], ul[3]);
    dl[1] = make_uint4(ul[4], ul[5], ul[6], ul[7]);
    dl[2] = make_uint4(ul[8], ul[9], ul[10], ul[11]);
    dl[3] = make_uint4(ul[12], ul[13], ul[14], ul[15]);
}

// ============================================================================
// Conv1 via mma.sync bf16x3 GEMM, A gathered from P1 (no im2col).
// Grid (t=64, mq=4, nq=2). 128 thr = 4 warps (1m x 4n), warp tile 64x64.
// 2-stage pipeline, 2 CTAs/SM.  (exact R10 kernel)
// ============================================================================
__global__ void __launch_bounds__(128, 2)
conv1_mma(const float* __restrict__ bias) {
    extern __shared__ __align__(128) char dsmem[];

    const int t    = blockIdx.x;
    const int mq   = blockIdx.y;
    const int nq   = blockIdx.z;
    const int tid  = threadIdx.x;
    const int warp = tid >> 5;
    const int lane = tid & 31;
    const int wn   = warp;

    const uint32_t abase = smem_u32(dsmem);

    const int aRow = ((lane >> 3) & 1) * 8 + (lane & 7);
    const int kA   = lane >> 4;
    const int sA   = aRow & 7;
    const int bRow = wn * 64 + ((lane >> 4) << 3) + (lane & 7);
    const int kB   = (lane >> 3) & 1;
    const int sB   = bRow & 7;

    float acc[4][8][4];
#pragma unroll
    for (int mi = 0; mi < 4; mi++)
#pragma unroll
        for (int ni = 0; ni < 8; ni++)
#pragma unroll
            for (int r = 0; r < 4; r++) acc[mi][ni][r] = 0.f;

    const size_t boff = (size_t)(nq * 256) * K1;

#define STAGE_LOAD1(CH, S)                                                     \
    {                                                                          \
        int seg = (CH) / 108;                                                  \
        int r   = (CH) - seg * 108;                                            \
        int tap = r >> 2, icc = r & 3;                                         \
        int kd = tap / 9, rr = tap - kd * 9, kh = rr / 3, kw = rr - kh * 3;    \
        const __nv_bfloat16* asrc = (seg == 1) ? g_p1l : g_p1h;                \
        const __nv_bfloat16* bsrc = (seg == 2) ? g_b1l : g_b1h;                \
        const size_t tb = (size_t)(t + kd) * (34 * 34 * 256) + icc * 64;       \
        uint32_t ab = abase + (S) * STAGE1_BYTES;                              \
        uint32_t bb = ab + 8192;                                               \
        _Pragma("unroll")                                                      \
        for (int j = 0; j < 4; j++) {                                          \
            int idx = tid + j * 128;                                           \
            int m = idx >> 3, kp = idx & 7;                                    \
            int mg = mq * 64 + m;                                              \
            int hp = 2 * (mg >> 4) + kh, wp = 2 * (mg & 15) + kw;              \
            cp16u(ab + m * 128 + ((kp ^ (m & 7)) << 4),                        \
                  asrc + tb + ((size_t)hp * 34 + wp) * 256 + kp * 8);          \
        }                                                                      \
        _Pragma("unroll")                                                      \
        for (int j = 0; j < 16; j++) {                                         \
            int idx = tid + j * 128;                                           \
            int oc = idx >> 3, kp = idx & 7;                                   \
            cp16u(bb + oc * 128 + ((kp ^ (oc & 7)) << 4),                      \
                  bsrc + boff + (size_t)oc * K1 + r * 64 + kp * 8);            \
        }                                                                      \
    }

    STAGE_LOAD1(0, 0);
    asm volatile("cp.async.commit_group;");

    for (int c = 0; c < NCHUNK1; c++) {
        if (c + 1 < NCHUNK1) {
            STAGE_LOAD1(c + 1, (c + 1) & 1);
            asm volatile("cp.async.commit_group;");
            asm volatile("cp.async.wait_group 1;");
        } else {
            asm volatile("cp.async.wait_group 0;");
        }
        __syncthreads();

        const uint32_t abuf = abase + (c & 1) * STAGE1_BYTES;
        const uint32_t aB = abuf + aRow * 128;
        const uint32_t bB = abuf + 8192 + bRow * 128;

#pragma unroll
        for (int ks = 0; ks < 4; ks++) {
            uint32_t a[4][4];
#pragma unroll
            for (int mi = 0; mi < 4; mi++) {
                uint32_t ad = aB + mi * 2048 + (((2 * ks + kA) ^ sA) << 4);
                asm volatile(
                    "ldmatrix.sync.aligned.m8n8.x4.shared.b16 {%0,%1,%2,%3}, [%4];"
                    : "=r"(a[mi][0]), "=r"(a[mi][1]), "=r"(a[mi][2]), "=r"(a[mi][3])
                    : "r"(ad));
            }
            uint32_t bg[8][2];
#pragma unroll
            for (int p = 0; p < 4; p++) {
                uint32_t bd = bB + p * 2048 + (((2 * ks + kB) ^ sB) << 4);
                asm volatile(
                    "ldmatrix.sync.aligned.m8n8.x4.shared.b16 {%0,%1,%2,%3}, [%4];"
                    : "=r"(bg[2 * p][0]), "=r"(bg[2 * p][1]),
                      "=r"(bg[2 * p + 1][0]), "=r"(bg[2 * p + 1][1])
                    : "r"(bd));
            }
#pragma unroll
            for (int mi = 0; mi < 4; mi++)
#pragma unroll
                for (int ni = 0; ni < 8; ni++)
                    asm volatile(
                        "mma.sync.aligned.m16n8k16.row.col.f32.bf16.bf16.f32 "
                        "{%0,%1,%2,%3}, {%4,%5,%6,%7}, {%8,%9}, {%0,%1,%2,%3};"
                        : "+f"(acc[mi][ni][0]), "+f"(acc[mi][ni][1]),
                          "+f"(acc[mi][ni][2]), "+f"(acc[mi][ni][3])
                        : "r"(a[mi][0]), "r"(a[mi][1]), "r"(a[mi][2]), "r"(a[mi][3]),
                          "r"(bg[ni][0]), "r"(bg[ni][1]));
        }
        __syncthreads();
    }
#undef STAGE_LOAD1

    // epilogue: bias + hi/lo bf16 -> P2 [t+1][h1+1][w1+1][oc]
    const int mbase = mq * 64 + (lane >> 2);
    const int ncb   = nq * 256 + wn * 64 + 2 * (lane & 3);
#pragma unroll
    for (int mi = 0; mi < 4; mi++) {
        int m0 = mbase + mi * 16;
        int m1 = m0 + 8;
        size_t row0 = (((size_t)(t + 1) * 18) + ((m0 >> 4) + 1)) * 18 + ((m0 & 15) + 1);
        size_t row1 = (((size_t)(t + 1) * 18) + ((m1 >> 4) + 1)) * 18 + ((m1 & 15) + 1);
#pragma unroll
        for (int ni = 0; ni < 8; ni++) {
            int n0 = ncb + ni * 8;
            float b0 = bias[n0], b1 = bias[n0 + 1];
            float v00 = acc[mi][ni][0] + b0, v01 = acc[mi][ni][1] + b1;
            float v10 = acc[mi][ni][2] + b0, v11 = acc[mi][ni][3] + b1;
            unsigned h0 = pack_bf2(v00, v01), h1 = pack_bf2(v10, v11);
            float r00 = v00 - __bfloat162float(__float2bfloat16(v00));
            float r01 = v01 - __bfloat162float(__float2bfloat16(v01));
            float r10 = v10 - __bfloat162float(__float2bfloat16(v10));
            float r11 = v11 - __bfloat162float(__float2bfloat16(v11));
            *(unsigned*)(g_p2h + row0 * 512 + n0) = h0;
            *(unsigned*)(g_p2h + row1 * 512 + n0) = h1;
            *(unsigned*)(g_p2l + row0 * 512 + n0) = pack_bf2(r00, r01);
            *(unsigned*)(g_p2l + row1 * 512 + n0) = pack_bf2(r10, r11);
        }
    }
}

// ============================================================================
// Conv2: bf16x3 mma.sync, t-paired tile M=128 x N=128, K-split x2.
// Grid (t2=32, nq=4, half=2) = 256 CTAs. 128 thr = 4 warps (2m x 2n),
// warp tile 64x64 (proven conv1 config). 3-stage, 2 CTAs/SM.
// Per chunk: 1M MACs for 32KB staging (2x R10 density, half the barriers).
// ============================================================================
__global__ void __launch_bounds__(128, 2)
conv2_mma() {
    extern __shared__ __align__(128) char dsmem[];

    const int t2   = blockIdx.x;         // 0..31, covers t = 2*t2, 2*t2+1
    const int nq   = blockIdx.y;         // 0..3, 128 oc each
    const int half = blockIdx.z;         // K half
    const int tid  = threadIdx.x;
    const int warp = tid >> 5;
    const int lane = tid & 31;
    const int wm   = warp >> 1;          // 0/1 -> t_local
    const int wn   = warp & 1;           // 0/1 -> N offset 64

    const uint32_t abase = smem_u32(dsmem);

    const int aRow = wm * 64 + ((lane >> 3) & 1) * 8 + (lane & 7);
    const int kA   = lane >> 4;
    const int sA   = aRow & 7;
    const int bRow = wn * 64 + ((lane >> 4) << 3) + (lane & 7);
    const int kB   = (lane >> 3) & 1;
    const int sB   = bRow & 7;

    float acc[4][8][4];
#pragma unroll
    for (int mi = 0; mi < 4; mi++)
#pragma unroll
        for (int ni = 0; ni < 8; ni++)
#pragma unroll
            for (int r = 0; r < 4; r++) acc[mi][ni][r] = 0.f;

    const size_t boff = (size_t)(nq * 128) * K2;
    const int gc0 = half * NCHUNK2H;

#define STAGE_LOAD2(GC, S)                                                     \
    {                                                                          \
        int seg = (GC) / 216;                                                  \
        int r   = (GC) - seg * 216;                                            \
        int tap = r >> 3, icc = r & 7;                                         \
        int kd = tap / 9, rr = tap - kd * 9, kh = rr / 3, kw = rr - kh * 3;    \
        const __nv_bfloat16* asrc = (seg == 1) ? g_p2l : g_p2h;                \
        const __nv_bfloat16* bsrc = (seg == 2) ? g_b2l : g_b2h;                \
        uint32_t ab = abase + (S) * STAGE2_BYTES;                              \
        uint32_t bb = ab + 16384;                                              \
        _Pragma("unroll")                                                      \
        for (int j = 0; j < 8; j++) {                                          \
            int idx = tid + j * 128;                                           \
            int m = idx >> 3, kp = idx & 7;                                    \
            int tl = m >> 6, p = m & 63;                                       \
            int hp = 2 * (p >> 3) + kh, wp = 2 * (p & 7) + kw;                 \
            cp16u(ab + m * 128 + ((kp ^ (m & 7)) << 4),                        \
                  asrc + (size_t)(t2 * 2 + tl + kd) * (18 * 18 * 512)          \
                       + ((size_t)hp * 18 + wp) * 512 + icc * 64 + kp * 8);    \
        }                                                                      \
        _Pragma("unroll")                                                      \
        for (int j = 0; j < 8; j++) {                                          \
            int idx = tid + j * 128;                                           \
            int oc = idx >> 3, kp = idx & 7;                                   \
            cp16u(bb + oc * 128 + ((kp ^ (oc & 7)) << 4),                      \
                  bsrc + boff + (size_t)oc * K2 + r * 64 + kp * 8);            \
        }                                                                      \
    }

    STAGE_LOAD2(gc0, 0);
    asm volatile("cp.async.commit_group;");
    STAGE_LOAD2(gc0 + 1, 1);
    asm volatile("cp.async.commit_group;");

    int sc = 0;
    for (int c = 0; c < NCHUNK2H; c++) {
        if (c + 1 < NCHUNK2H) asm volatile("cp.async.wait_group 1;");
        else                  asm volatile("cp.async.wait_group 0;");
        __syncthreads();
        if (c + 2 < NCHUNK2H) {
            int sn = sc + 2; if (sn >= 3) sn -= 3;
            STAGE_LOAD2(gc0 + c + 2, sn);
            asm volatile("cp.async.commit_group;");
        }

        const uint32_t abuf = abase + sc * STAGE2_BYTES;
        const uint32_t aB = abuf + aRow * 128;
        const uint32_t bB = abuf + 16384 + bRow * 128;

#pragma unroll
        for (int ks = 0; ks < 4; ks++) {
            uint32_t a[4][4];
#pragma unroll
            for (int mi = 0; mi < 4; mi++) {
                uint32_t ad = aB + mi * 2048 + (((2 * ks + kA) ^ sA) << 4);
                asm volatile(
                    "ldmatrix.sync.aligned.m8n8.x4.shared.b16 {%0,%1,%2,%3}, [%4];"
                    : "=r"(a[mi][0]), "=r"(a[mi][1]), "=r"(a[mi][2]), "=r"(a[mi][3])
                    : "r"(ad));
            }
            uint32_t bg[8][2];
#pragma unroll
            for (int p = 0; p < 4; p++) {
                uint32_t bd = bB + p * 2048 + (((2 * ks + kB) ^ sB) << 4);
                asm volatile(
                    "ldmatrix.sync.aligned.m8n8.x4.shared.b16 {%0,%1,%2,%3}, [%4];"
                    : "=r"(bg[2 * p][0]), "=r"(bg[2 * p][1]),
                      "=r"(bg[2 * p + 1][0]), "=r"(bg[2 * p + 1][1])
                    : "r"(bd));
            }
#pragma unroll
            for (int mi = 0; mi < 4; mi++)
#pragma unroll
                for (int ni = 0; ni < 8; ni++)
                    asm volatile(
                        "mma.sync.aligned.m16n8k16.row.col.f32.bf16.bf16.f32 "
                        "{%0,%1,%2,%3}, {%4,%5,%6,%7}, {%8,%9}, {%0,%1,%2,%3};"
                        : "+f"(acc[mi][ni][0]), "+f"(acc[mi][ni][1]),
                          "+f"(acc[mi][ni][2]), "+f"(acc[mi][ni][3])
                        : "r"(a[mi][0]), "r"(a[mi][1]), "r"(a[mi][2]), "r"(a[mi][3]),
                          "r"(bg[ni][0]), "r"(bg[ni][1]));
        }
        __syncthreads();
        if (++sc == 3) sc = 0;
    }
#undef STAGE_LOAD2

    // write fp32 partials: g_part[half][t2*2+wm][pos][oc]
    float* pb = g_part + ((size_t)(half * 64 + t2 * 2 + wm) * 64) * 512;
    const int prow = lane >> 2;
    const int ncb  = nq * 128 + wn * 64 + 2 * (lane & 3);
#pragma unroll
    for (int mi = 0; mi < 4; mi++) {
        int p0 = prow + mi * 16;
        int p1 = p0 + 8;
#pragma unroll
        for (int ni = 0; ni < 8; ni++) {
            int n0 = ncb + ni * 8;
            *(float2*)(pb + (size_t)p0 * 512 + n0) =
                make_float2(acc[mi][ni][0], acc[mi][ni][1]);
            *(float2*)(pb + (size_t)p1 * 512 + n0) =
                make_float2(acc[mi][ni][2], acc[mi][ni][3]);
        }
    }
}

// ============================================================================
// reduce2: sum K-halves, max over 64 positions, + bias -> g_feat
// ============================================================================
__global__ void __launch_bounds__(512)
reduce2(const float* __restrict__ bias) {
    const int t  = blockIdx.x;
    const int oc = threadIdx.x;
    const float* p0 = g_part + (size_t)t * 64 * 512;
    const float* p1 = g_part + (size_t)(64 + t) * 64 * 512;
    float mx = -3.4e38f;
#pragma unroll 8
    for (int m = 0; m < 64; m++)
        mx = fmaxf(mx, p0[(size_t)m * 512 + oc] + p1[(size_t)m * 512 + oc]);
    g_feat[oc * TT + t] = mx + bias[oc];
}

// ============================================================================
// Head (unchanged, passing since R1)
// ============================================================================
__device__ __forceinline__ float iou1d(float s1, float e1, float s2, float e2) {
    float inter = fmaxf(fminf(e1, e2) - fmaxf(s1, s2), 0.f);
    float uni   = (e1 - s1) + (e2 - s2) - inter;
    return inter / fmaxf(uni, 1e-6f);
}

__global__ void __launch_bounds__(512, 1)
head_kernel(const float* __restrict__ sw, const float* __restrict__ sb,
            const float* __restrict__ dw, const float* __restrict__ db,
            const float* __restrict__ gt, const int* __restrict__ vlen,
            float* __restrict__ out) {
    __shared__ float s_sl[16 * 64], s_dl[16 * 64];
    __shared__ float s_bs[NANCH], s_be[NANCH], s_sc[NANCH];
    __shared__ float s_as[NANCH], s_ae[NANCH];
    __shared__ float s_lp0[NANCH], s_lp1[NANCH], s_dc[NANCH], s_dt[NANCH];
    __shared__ float s_gt[16];
    __shared__ int   s_best[8];
    __shared__ float r0[512], r1[512], r2[512], r3[512];

    const int tid  = threadIdx.x;
    const int wid  = tid >> 5;
    const int lane = tid & 31;
    if (tid < 16) s_gt[tid] = gt[tid];

    const int o = tid >> 6;
    const int t = tid & 63;
    {
        float a0 = sb[o], a1 = sb[o + 8], d0 = db[o], d1 = db[o + 8];
        for (int c = 0; c < C2; c++) {
            float f = g_feat[c * 64 + t];
            a0 = fmaf(sw[o * 512 + c],       f, a0);
            a1 = fmaf(sw[(o + 8) * 512 + c], f, a1);
            d0 = fmaf(dw[o * 512 + c],       f, d0);
            d1 = fmaf(dw[(o + 8) * 512 + c], f, d1);
        }
        s_sl[o * 64 + t] = a0;  s_sl[(o + 8) * 64 + t] = a1;
        s_dl[o * 64 + t] = d0;  s_dl[(o + 8) * 64 + t] = d1;
    }
    __syncthreads();

    {
        const int a = o;
        float l0 = s_sl[a * 64 + t], l1 = s_sl[(a + 8) * 64 + t];
        float mx = fmaxf(l0, l1);
        float lse = mx + logf(expf(l0 - mx) + expf(l1 - mx));
        float p1  = expf(l1 - lse);
        float dc  = s_dl[a * 64 + t], dl = s_dl[(a + 8) * 64 + t];
        float alen = (float)(8 << a);
        float ctr  = (t + 0.5f) * 8.f;
        float pc = ctr + dc * alen;
        float pl = alen * expf(fminf(fmaxf(dl, -10.f), 10.f));
        float ps = fminf(fmaxf(pc - 0.5f * pl, 0.f), 512.f);
        float pe = fminf(fmaxf(pc + 0.5f * pl, 0.f), 512.f);
        s_bs[tid] = ps;  s_be[tid] = pe;
        s_sc[tid] = (pe - ps >= 4.f) ? p1 : -1.0e9f;
        s_as[tid] = ctr - 0.5f * alen;
        s_ae[tid] = ctr + 0.5f * alen;
        s_lp0[tid] = l0 - lse;  s_lp1[tid] = l1 - lse;
        s_dc[tid] = dc;  s_dt[tid] = dl;
    }
    __syncthreads();

    if (wid < 8) {
        float gs = s_gt[wid * 2], ge = s_gt[wid * 2 + 1];
        float bv = -3.4e38f; int bi = 0x7fffffff;
        for (int k = 0; k < 16; k++) {
            int n = lane + 32 * k;
            float v = iou1d(s_as[n], s_ae[n], gs, ge);
            if (v > bv) { bv = v; bi = n; }
        }
        for (int off = 16; off; off >>= 1) {
            float ov = __shfl_xor_sync(0xffffffffu, bv, off);
            int   oi = __shfl_xor_sync(0xffffffffu, bi, off);
            if (ov > bv || (ov == bv && oi < bi)) { bv = ov; bi = oi; }
        }
        if (lane == 0) s_best[wid] = bi;
    }
    __syncthreads();

    {
        float myas = s_as[tid], myae = s_ae[tid];
        float miou = -1.f; int ag = 0;
#pragma unroll
        for (int g = 0; g < 8; g++) {
            float v = iou1d(myas, myae, s_gt[2 * g], s_gt[2 * g + 1]);
            if (v > miou) { miou = v; ag = g; }
        }
        int lab = (miou < 0.3f) ? 0 : -1;
        if (miou >= 0.7f) lab = 1;
#pragma unroll
        for (int g = 0; g < 8; g++)
            if (s_best[g] == tid) lab = 1;
        float vl = (float)vlen[0];
        if (!(myas >= 0.f && myae <= vl)) lab = -1;

        float gs = s_gt[2 * ag], ge = s_gt[2 * ag + 1];
        float gc = 0.5f * (gs + ge);
        float gl = fmaxf(ge - gs, 1e-6f);
        float ac = 0.5f * (myas + myae);
        float al = myae - myas;
        float rl0 = (gc - ac) / al;
        float rl1 = logf(gl / al);
        float d0 = s_dc[tid] - rl0, d1 = s_dt[tid] - rl1;
        float sl1 = (fabsf(d0) < 1.f ? 0.5f * d0 * d0 : fabsf(d0) - 0.5f)
                  + (fabsf(d1) < 1.f ? 0.5f * d1 * d1 : fabsf(d1) - 0.5f);
        float maskv = (lab >= 0) ? 1.f : 0.f;
        float posv  = (lab == 1) ? 1.f : 0.f;
        float nll   = -((lab == 1) ? s_lp1[tid] : s_lp0[tid]);
        r0[tid] = nll * maskv;  r1[tid] = maskv;
        r2[tid] = sl1 * posv;   r3[tid] = posv;
    }
    __syncthreads();
    for (int s = 256; s > 0; s >>= 1) {
        if (tid < s) {
            r0[tid] += r0[tid + s];  r1[tid] += r1[tid + s];
            r2[tid] += r2[tid + s];  r3[tid] += r3[tid + s];
        }
        __syncthreads();
    }
    if (tid == 0) {
        out[300] = r0[0] / fmaxf(r1[0], 1.f);
        out[301] = r2[0] / fmaxf(r3[0], 1.f);
    }
    __syncthreads();

    if (wid == 0) {
        for (int it = 0; it < 100; it++) {
            float bv = -3.4e38f; int bi = 0x7fffffff;
#pragma unroll
            for (int k = 0; k < 16; k++) {
                int n = lane + 32 * k;
                float v = s_sc[n];
                if (v > bv) { bv = v; bi = n; }
            }
            for (int off = 16; off; off >>= 1) {
                float ov = __shfl_xor_sync(0xffffffffu, bv, off);
                int   oi = __shfl_xor_sync(0xffffffffu, bi, off);
                if (ov > bv || (ov == bv && oi < bi)) { bv = ov; bi = oi; }
            }
            float kb0 = s_bs[bi], kb1 = s_be[bi];
            bool keep = bv > -5.0e8f;
            if (lane == 0) {
                out[2 * it]     = keep ? kb0 : 0.f;
                out[2 * it + 1] = keep ? kb1 : 0.f;
                out[200 + it]   = keep ? bv  : 0.f;
            }
#pragma unroll
            for (int k = 0; k < 16; k++) {
                int n = lane + 32 * k;
                float v = iou1d(kb0, kb1, s_bs[n], s_be[n]);
                if (v > 0.7f || n == bi) s_sc[n] = -1.0e9f;
            }
            __syncwarp();
        }
    }
}

// ============================================================================
extern "C" void kernel_launch(void* const* d_in, const int* in_sizes, int n_in,
                              void* d_out, int out_size) {
    const float* base = (const float*)d_in[0];
    const float* gt   = (const float*)d_in[1];
    const int*   vl   = (const int*)d_in[2];
    const float* c1w  = (const float*)d_in[3];
    const float* c1b  = (const float*)d_in[4];
    const float* c2w  = (const float*)d_in[5];
    const float* c2b  = (const float*)d_in[6];
    const float* sw   = (const float*)d_in[7];
    const float* sb   = (const float*)d_in[8];
    const float* dw   = (const float*)d_in[9];
    const float* db   = (const float*)d_in[10];
    float* out = (float*)d_out;

    static int attr_set = 0;
    if (!attr_set) {
        cudaFuncSetAttribute(conv1_mma,
                             cudaFuncAttributeMaxDynamicSharedMemorySize, C1MMA_SMEM);
        cudaFuncSetAttribute(conv2_mma,
                             cudaFuncAttributeMaxDynamicSharedMemorySize, C2MMA_SMEM);
        attr_set = 1;
    }

    void *p1h, *p1l, *p2h, *p2l;
    cudaGetSymbolAddress(&p1h, g_p1h);
    cudaGetSymbolAddress(&p1l, g_p1l);
    cudaGetSymbolAddress(&p2h, g_p2h);
    cudaGetSymbolAddress(&p2l, g_p2l);

    memzero<<<1024, 256>>>((uint4*)p1h, P1_ELEMS * 2 / 16);
    memzero<<<1024, 256>>>((uint4*)p1l, P1_ELEMS * 2 / 16);
    memzero<<<1024, 256>>>((uint4*)p2h, P2_ELEMS * 2 / 16);
    memzero<<<1024, 256>>>((uint4*)p2l, P2_ELEMS * 2 / 16);
    split_w1<<<512, 256>>>(c1w);
    split_w2<<<512, 256>>>(c2w);
    pad_split1<<<dim3(64, 32), 256>>>(base);
    conv1_mma<<<dim3(64, 4, 2), 128, C1MMA_SMEM>>>(c1b);
    conv2_mma<<<dim3(32, 4, 2), 128, C2MMA_SMEM>>>();
    reduce2<<<64, 512>>>(c2b);
    head_kernel<<<1, 512>>>(sw, sb, dw, db, gt, vl, out);
}

// round 14
// speedup vs baseline: 1.0305x; 1.0305x over previous
#include <cuda_runtime.h>
#include <cuda_bf16.h>
#include <cstdint>

typedef unsigned long long ull;

// ---------------- problem constants ----------------
#define CIN   256
#define TT    64
#define HIN   32
#define WIN   32
#define C1    512
#define C2    512
#define NANCH 512

// conv1 GEMM: K1 = 27 taps * 256 ic (tap-major: k = tap*256 + ic)
#define K1      6912
#define NCHUNK1 324            // 3 segments * 108 (27 tap * 4 icc)
#define STAGE1_BYTES 40960     // A 8KB + B 32KB
#define C1MMA_SMEM  (2 * STAGE1_BYTES)   // 80KB, 2 CTAs/SM

// conv2 GEMM: K2 = 27 taps * 512 ic (tap-major), K-split x2 by ic-group
#define K2      13824
#define NCHUNK2H 324           // per K-half: 3 seg * 27 tap * 4 icc
#define STAGE2_BYTES 40960     // A 8KB + B 32KB (conv1-clone)
#define C2MMA_SMEM  (2 * STAGE2_BYTES)   // 80KB, 2 CTAs/SM

// padded activation tensors (ic innermost)
#define P1_ELEMS ((size_t)66 * 34 * 34 * 256)
#define P2_ELEMS ((size_t)66 * 18 * 18 * 512)

// ---------------- device scratch ----------------
__device__ __align__(16) __nv_bfloat16 g_p1h[P1_ELEMS];          // 39 MB
__device__ __align__(16) __nv_bfloat16 g_p1l[P1_ELEMS];          // 39 MB
__device__ __align__(16) __nv_bfloat16 g_p2h[P2_ELEMS];          // 22 MB
__device__ __align__(16) __nv_bfloat16 g_p2l[P2_ELEMS];          // 22 MB
__device__ __align__(16) __nv_bfloat16 g_b1h[(size_t)C1 * K1];   //  7 MB
__device__ __align__(16) __nv_bfloat16 g_b1l[(size_t)C1 * K1];   //  7 MB
__device__ __align__(16) __nv_bfloat16 g_b2h[(size_t)C2 * K2];   // 14 MB
__device__ __align__(16) __nv_bfloat16 g_b2l[(size_t)C2 * K2];   // 14 MB
__device__ float g_part[(size_t)2 * 64 * 64 * 512];              // 16.8 MB
__device__ float g_feat[C2 * TT];

// ---------------- helpers ----------------
__device__ __forceinline__ void cp16u(unsigned dst, const void* src) {
    asm volatile("cp.async.cg.shared.global [%0], [%1], 16;" :: "r"(dst), "l"(src));
}
__device__ __forceinline__ uint32_t smem_u32(const void* p) {
    return (uint32_t)__cvta_generic_to_shared(p);
}
__device__ __forceinline__ unsigned pack_bf2(float a, float b) {
    __nv_bfloat162 p = __floats2bfloat162_rn(a, b);
    return *reinterpret_cast<unsigned*>(&p);
}

// ============================================================================
// memzero (halo init for P1/P2)
// ============================================================================
__global__ void memzero(uint4* p, size_t n) {
    size_t i = (size_t)blockIdx.x * blockDim.x + threadIdx.x;
    size_t stride = (size_t)gridDim.x * blockDim.x;
    uint4 z = make_uint4(0u, 0u, 0u, 0u);
    for (; i < n; i += stride) p[i] = z;
}

// ============================================================================
// split_w1: w1[oc][ic*27+tap] -> b1 [oc][tap*256+ic] hi/lo
// ============================================================================
__global__ void split_w1(const float* __restrict__ w) {
    int oc = blockIdx.x;
    const float* src = w + (size_t)oc * K1;
    __nv_bfloat16* dh = g_b1h + (size_t)oc * K1;
    __nv_bfloat16* dl = g_b1l + (size_t)oc * K1;
#pragma unroll 3
    for (int j = 0; j < 27; j++) {
        int k = threadIdx.x + j * 256;
        int tap = k >> 8, ic = k & 255;
        float v = src[ic * 27 + tap];
        __nv_bfloat16 hi = __float2bfloat16(v);
        dh[k] = hi;
        dl[k] = __float2bfloat16(v - __bfloat162float(hi));
    }
}

// ============================================================================
// split_w2: w2[oc][ic*27+tap] -> b2 [oc][tap*512+ic] hi/lo
// ============================================================================
__global__ void split_w2(const float* __restrict__ w) {
    int oc = blockIdx.x;
    const float* src = w + (size_t)oc * (512 * 27);
    __nv_bfloat16* dh = g_b2h + (size_t)oc * K2;
    __nv_bfloat16* dl = g_b2l + (size_t)oc * K2;
#pragma unroll 6
    for (int j = 0; j < 54; j++) {
        int k = threadIdx.x + j * 256;
        int tap = k >> 9, ic = k & 511;
        float v = src[ic * 27 + tap];
        __nv_bfloat16 hi = __float2bfloat16(v);
        dh[k] = hi;
        dl[k] = __float2bfloat16(v - __bfloat162float(hi));
    }
}

// ============================================================================
// pad_split1: input [ic][t][h][w] fp32 -> P1 [t+1][h+1][w+1][ic] hi/lo bf16
// ============================================================================
__global__ void __launch_bounds__(256)
pad_split1(const float* __restrict__ in) {
    __shared__ float sm[256 * 33];
    const int t = blockIdx.x;
    const int h = blockIdx.y;
    const int tid = threadIdx.x;

#pragma unroll 8
    for (int j = 0; j < 32; j++) {
        int k = tid + j * 256;
        int ic = k >> 5, w = k & 31;
        sm[ic * 33 + w] = in[((size_t)(ic * TT + t) * HIN + h) * WIN + w];
    }
    __syncthreads();

    const int w   = tid >> 3;
    const int icg = tid & 7;
    float v[32];
#pragma unroll
    for (int i = 0; i < 32; i++) {
        int jj = i ^ (icg << 2);
        v[jj] = sm[(icg * 32 + jj) * 33 + w];
    }
    unsigned uh[16], ul[16];
#pragma unroll
    for (int p = 0; p < 16; p++) {
        float a = v[2 * p], b = v[2 * p + 1];
        uh[p] = pack_bf2(a, b);
        float ah = __bfloat162float(__float2bfloat16(a));
        float bh = __bfloat162float(__float2bfloat16(b));
        ul[p] = pack_bf2(a - ah, b - bh);
    }
    const size_t row = (((size_t)(t + 1) * 34) + (h + 1)) * 34 + (w + 1);
    uint4* dh = (uint4*)(g_p1h + row * 256 + icg * 32);
    uint4* dl = (uint4*)(g_p1l + row * 256 + icg * 32);
    dh[0] = make_uint4(uh[0], uh[1], uh[2], uh[3]);
    dh[1] = make_uint4(uh[4], uh[5], uh[6], uh[7]);
    dh[2] = make_uint4(uh[8], uh[9], uh[10], uh[11]);
    dh[3] = make_uint4(uh[12], uh[13], uh[14], uh[15]);
    dl[0] = make_uint4(ul[0], ul[1], ul[2], ul[3]);
    dl[1] = make_uint4(ul[4], ul[5], ul[6], ul[7]);
    dl[2] = make_uint4(ul[8], ul[9], ul[10], ul[11]);
    dl[3] = make_uint4(ul[12], ul[13], ul[14], ul[15]);
}

// ============================================================================
// Conv1 via mma.sync bf16x3 GEMM, A gathered from P1 (no im2col).
// Grid (t=64, mq=4, nq=2). 128 thr = 4 warps (1m x 4n), warp tile 64x64.
// 2-stage pipeline, 2 CTAs/SM.  (exact R10 kernel)
// ============================================================================
__global__ void __launch_bounds__(128, 2)
conv1_mma(const float* __restrict__ bias) {
    extern __shared__ __align__(128) char dsmem[];

    const int t    = blockIdx.x;
    const int mq   = blockIdx.y;
    const int nq   = blockIdx.z;
    const int tid  = threadIdx.x;
    const int warp = tid >> 5;
    const int lane = tid & 31;
    const int wn   = warp;

    const uint32_t abase = smem_u32(dsmem);

    const int aRow = ((lane >> 3) & 1) * 8 + (lane & 7);
    const int kA   = lane >> 4;
    const int sA   = aRow & 7;
    const int bRow = wn * 64 + ((lane >> 4) << 3) + (lane & 7);
    const int kB   = (lane >> 3) & 1;
    const int sB   = bRow & 7;

    float acc[4][8][4];
#pragma unroll
    for (int mi = 0; mi < 4; mi++)
#pragma unroll
        for (int ni = 0; ni < 8; ni++)
#pragma unroll
            for (int r = 0; r < 4; r++) acc[mi][ni][r] = 0.f;

    const size_t boff = (size_t)(nq * 256) * K1;

#define STAGE_LOAD1(CH, S)                                                     \
    {                                                                          \
        int seg = (CH) / 108;                                                  \
        int r   = (CH) - seg * 108;                                            \
        int tap = r >> 2, icc = r & 3;                                         \
        int kd = tap / 9, rr = tap - kd * 9, kh = rr / 3, kw = rr - kh * 3;    \
        const __nv_bfloat16* asrc = (seg == 1) ? g_p1l : g_p1h;                \
        const __nv_bfloat16* bsrc = (seg == 2) ? g_b1l : g_b1h;                \
        const size_t tb = (size_t)(t + kd) * (34 * 34 * 256) + icc * 64;       \
        uint32_t ab = abase + (S) * STAGE1_BYTES;                              \
        uint32_t bb = ab + 8192;                                               \
        _Pragma("unroll")                                                      \
        for (int j = 0; j < 4; j++) {                                          \
            int idx = tid + j * 128;                                           \
            int m = idx >> 3, kp = idx & 7;                                    \
            int mg = mq * 64 + m;                                              \
            int hp = 2 * (mg >> 4) + kh, wp = 2 * (mg & 15) + kw;              \
            cp16u(ab + m * 128 + ((kp ^ (m & 7)) << 4),                        \
                  asrc + tb + ((size_t)hp * 34 + wp) * 256 + kp * 8);          \
        }                                                                      \
        _Pragma("unroll")                                                      \
        for (int j = 0; j < 16; j++) {                                         \
            int idx = tid + j * 128;                                           \
            int oc = idx >> 3, kp = idx & 7;                                   \
            cp16u(bb + oc * 128 + ((kp ^ (oc & 7)) << 4),                      \
                  bsrc + boff + (size_t)oc * K1 + r * 64 + kp * 8);            \
        }                                                                      \
    }

    STAGE_LOAD1(0, 0);
    asm volatile("cp.async.commit_group;");

    for (int c = 0; c < NCHUNK1; c++) {
        if (c + 1 < NCHUNK1) {
            STAGE_LOAD1(c + 1, (c + 1) & 1);
            asm volatile("cp.async.commit_group;");
            asm volatile("cp.async.wait_group 1;");
        } else {
            asm volatile("cp.async.wait_group 0;");
        }
        __syncthreads();

        const uint32_t abuf = abase + (c & 1) * STAGE1_BYTES;
        const uint32_t aB = abuf + aRow * 128;
        const uint32_t bB = abuf + 8192 + bRow * 128;

#pragma unroll
        for (int ks = 0; ks < 4; ks++) {
            uint32_t a[4][4];
#pragma unroll
            for (int mi = 0; mi < 4; mi++) {
                uint32_t ad = aB + mi * 2048 + (((2 * ks + kA) ^ sA) << 4);
                asm volatile(
                    "ldmatrix.sync.aligned.m8n8.x4.shared.b16 {%0,%1,%2,%3}, [%4];"
                    : "=r"(a[mi][0]), "=r"(a[mi][1]), "=r"(a[mi][2]), "=r"(a[mi][3])
                    : "r"(ad));
            }
            uint32_t bg[8][2];
#pragma unroll
            for (int p = 0; p < 4; p++) {
                uint32_t bd = bB + p * 2048 + (((2 * ks + kB) ^ sB) << 4);
                asm volatile(
                    "ldmatrix.sync.aligned.m8n8.x4.shared.b16 {%0,%1,%2,%3}, [%4];"
                    : "=r"(bg[2 * p][0]), "=r"(bg[2 * p][1]),
                      "=r"(bg[2 * p + 1][0]), "=r"(bg[2 * p + 1][1])
                    : "r"(bd));
            }
#pragma unroll
            for (int mi = 0; mi < 4; mi++)
#pragma unroll
                for (int ni = 0; ni < 8; ni++)
                    asm volatile(
                        "mma.sync.aligned.m16n8k16.row.col.f32.bf16.bf16.f32 "
                        "{%0,%1,%2,%3}, {%4,%5,%6,%7}, {%8,%9}, {%0,%1,%2,%3};"
                        : "+f"(acc[mi][ni][0]), "+f"(acc[mi][ni][1]),
                          "+f"(acc[mi][ni][2]), "+f"(acc[mi][ni][3])
                        : "r"(a[mi][0]), "r"(a[mi][1]), "r"(a[mi][2]), "r"(a[mi][3]),
                          "r"(bg[ni][0]), "r"(bg[ni][1]));
        }
        __syncthreads();
    }
#undef STAGE_LOAD1

    // epilogue: bias + hi/lo bf16 -> P2 [t+1][h1+1][w1+1][oc]
    const int mbase = mq * 64 + (lane >> 2);
    const int ncb   = nq * 256 + wn * 64 + 2 * (lane & 3);
#pragma unroll
    for (int mi = 0; mi < 4; mi++) {
        int m0 = mbase + mi * 16;
        int m1 = m0 + 8;
        size_t row0 = (((size_t)(t + 1) * 18) + ((m0 >> 4) + 1)) * 18 + ((m0 & 15) + 1);
        size_t row1 = (((size_t)(t + 1) * 18) + ((m1 >> 4) + 1)) * 18 + ((m1 & 15) + 1);
#pragma unroll
        for (int ni = 0; ni < 8; ni++) {
            int n0 = ncb + ni * 8;
            float b0 = bias[n0], b1 = bias[n0 + 1];
            float v00 = acc[mi][ni][0] + b0, v01 = acc[mi][ni][1] + b1;
            float v10 = acc[mi][ni][2] + b0, v11 = acc[mi][ni][3] + b1;
            unsigned h0 = pack_bf2(v00, v01), h1 = pack_bf2(v10, v11);
            float r00 = v00 - __bfloat162float(__float2bfloat16(v00));
            float r01 = v01 - __bfloat162float(__float2bfloat16(v01));
            float r10 = v10 - __bfloat162float(__float2bfloat16(v10));
            float r11 = v11 - __bfloat162float(__float2bfloat16(v11));
            *(unsigned*)(g_p2h + row0 * 512 + n0) = h0;
            *(unsigned*)(g_p2h + row1 * 512 + n0) = h1;
            *(unsigned*)(g_p2l + row0 * 512 + n0) = pack_bf2(r00, r01);
            *(unsigned*)(g_p2l + row1 * 512 + n0) = pack_bf2(r10, r11);
        }
    }
}

// ============================================================================
// Conv2: conv1-clone shape. M=64 x N=256, K-split x2 (by ic-group).
// Grid (t=64, nq=2, half=2) = 256 CTAs. 4 warps (1m x 4n), warp tile 64x64.
// 2-stage, A 8KB + B 32KB per chunk, 324 chunks. 2 CTAs/SM.
// fp32 partials -> g_part, reduced by reduce2.
// ============================================================================
__global__ void __launch_bounds__(128, 2)
conv2_mma() {
    extern __shared__ __align__(128) char dsmem[];

    const int t    = blockIdx.x;
    const int nq   = blockIdx.y;         // 0/1 -> 256 oc each
    const int half = blockIdx.z;         // ic-group half
    const int tid  = threadIdx.x;
    const int warp = tid >> 5;
    const int lane = tid & 31;
    const int wn   = warp;

    const uint32_t abase = smem_u32(dsmem);

    const int aRow = ((lane >> 3) & 1) * 8 + (lane & 7);
    const int kA   = lane >> 4;
    const int sA   = aRow & 7;
    const int bRow = wn * 64 + ((lane >> 4) << 3) + (lane & 7);
    const int kB   = (lane >> 3) & 1;
    const int sB   = bRow & 7;

    float acc[4][8][4];
#pragma unroll
    for (int mi = 0; mi < 4; mi++)
#pragma unroll
        for (int ni = 0; ni < 8; ni++)
#pragma unroll
            for (int r = 0; r < 4; r++) acc[mi][ni][r] = 0.f;

    const size_t boff = (size_t)(nq * 256) * K2;

#define STAGE_LOAD2(CH, S)                                                     \
    {                                                                          \
        int seg = (CH) / 108;                                                  \
        int r   = (CH) - seg * 108;                                            \
        int tap = r >> 2, icc = (half << 2) | (r & 3);                         \
        int kd = tap / 9, rr = tap - kd * 9, kh = rr / 3, kw = rr - kh * 3;    \
        const __nv_bfloat16* asrc = (seg == 1) ? g_p2l : g_p2h;                \
        const __nv_bfloat16* bsrc = (seg == 2) ? g_b2l : g_b2h;                \
        const size_t tb = (size_t)(t + kd) * (18 * 18 * 512) + icc * 64;       \
        const size_t bk = (size_t)tap * 512 + icc * 64;                        \
        uint32_t ab = abase + (S) * STAGE2_BYTES;                              \
        uint32_t bb = ab + 8192;                                               \
        _Pragma("unroll")                                                      \
        for (int j = 0; j < 4; j++) {                                          \
            int idx = tid + j * 128;                                           \
            int m = idx >> 3, kp = idx & 7;                                    \
            int hp = 2 * (m >> 3) + kh, wp = 2 * (m & 7) + kw;                 \
            cp16u(ab + m * 128 + ((kp ^ (m & 7)) << 4),                        \
                  asrc + tb + ((size_t)hp * 18 + wp) * 512 + kp * 8);          \
        }                                                                      \
        _Pragma("unroll")                                                      \
        for (int j = 0; j < 16; j++) {                                         \
            int idx = tid + j * 128;                                           \
            int oc = idx >> 3, kp = idx & 7;                                   \
            cp16u(bb + oc * 128 + ((kp ^ (oc & 7)) << 4),                      \
                  bsrc + boff + (size_t)oc * K2 + bk + kp * 8);                \
        }                                                                      \
    }

    STAGE_LOAD2(0, 0);
    asm volatile("cp.async.commit_group;");

    for (int c = 0; c < NCHUNK2H; c++) {
        if (c + 1 < NCHUNK2H) {
            STAGE_LOAD2(c + 1, (c + 1) & 1);
            asm volatile("cp.async.commit_group;");
            asm volatile("cp.async.wait_group 1;");
        } else {
            asm volatile("cp.async.wait_group 0;");
        }
        __syncthreads();

        const uint32_t abuf = abase + (c & 1) * STAGE2_BYTES;
        const uint32_t aB = abuf + aRow * 128;
        const uint32_t bB = abuf + 8192 + bRow * 128;

#pragma unroll
        for (int ks = 0; ks < 4; ks++) {
            uint32_t a[4][4];
#pragma unroll
            for (int mi = 0; mi < 4; mi++) {
                uint32_t ad = aB + mi * 2048 + (((2 * ks + kA) ^ sA) << 4);
                asm volatile(
                    "ldmatrix.sync.aligned.m8n8.x4.shared.b16 {%0,%1,%2,%3}, [%4];"
                    : "=r"(a[mi][0]), "=r"(a[mi][1]), "=r"(a[mi][2]), "=r"(a[mi][3])
                    : "r"(ad));
            }
            uint32_t bg[8][2];
#pragma unroll
            for (int p = 0; p < 4; p++) {
                uint32_t bd = bB + p * 2048 + (((2 * ks + kB) ^ sB) << 4);
                asm volatile(
                    "ldmatrix.sync.aligned.m8n8.x4.shared.b16 {%0,%1,%2,%3}, [%4];"
                    : "=r"(bg[2 * p][0]), "=r"(bg[2 * p][1]),
                      "=r"(bg[2 * p + 1][0]), "=r"(bg[2 * p + 1][1])
                    : "r"(bd));
            }
#pragma unroll
            for (int mi = 0; mi < 4; mi++)
#pragma unroll
                for (int ni = 0; ni < 8; ni++)
                    asm volatile(
                        "mma.sync.aligned.m16n8k16.row.col.f32.bf16.bf16.f32 "
                        "{%0,%1,%2,%3}, {%4,%5,%6,%7}, {%8,%9}, {%0,%1,%2,%3};"
                        : "+f"(acc[mi][ni][0]), "+f"(acc[mi][ni][1]),
                          "+f"(acc[mi][ni][2]), "+f"(acc[mi][ni][3])
                        : "r"(a[mi][0]), "r"(a[mi][1]), "r"(a[mi][2]), "r"(a[mi][3]),
                          "r"(bg[ni][0]), "r"(bg[ni][1]));
        }
        __syncthreads();
    }
#undef STAGE_LOAD2

    // write fp32 partials: g_part[half][t][m][oc]
    float* pb = g_part + ((size_t)(half * 64 + t) * 64) * 512;
    const int mrow = lane >> 2;
    const int ncb  = nq * 256 + wn * 64 + 2 * (lane & 3);
#pragma unroll
    for (int mi = 0; mi < 4; mi++) {
        int m0 = mrow + mi * 16;
        int m1 = m0 + 8;
#pragma unroll
        for (int ni = 0; ni < 8; ni++) {
            int n0 = ncb + ni * 8;
            *(float2*)(pb + (size_t)m0 * 512 + n0) =
                make_float2(acc[mi][ni][0], acc[mi][ni][1]);
            *(float2*)(pb + (size_t)m1 * 512 + n0) =
                make_float2(acc[mi][ni][2], acc[mi][ni][3]);
        }
    }
}

// ============================================================================
// reduce2: sum K-halves, max over 64 positions, + bias -> g_feat
// ============================================================================
__global__ void __launch_bounds__(512)
reduce2(const float* __restrict__ bias) {
    const int t  = blockIdx.x;
    const int oc = threadIdx.x;
    const float* p0 = g_part + (size_t)t * 64 * 512;
    const float* p1 = g_part + (size_t)(64 + t) * 64 * 512;
    float mx = -3.4e38f;
#pragma unroll 8
    for (int m = 0; m < 64; m++)
        mx = fmaxf(mx, p0[(size_t)m * 512 + oc] + p1[(size_t)m * 512 + oc]);
    g_feat[oc * TT + t] = mx + bias[oc];
}

// ============================================================================
// Head (unchanged, passing since R1)
// ============================================================================
__device__ __forceinline__ float iou1d(float s1, float e1, float s2, float e2) {
    float inter = fmaxf(fminf(e1, e2) - fmaxf(s1, s2), 0.f);
    float uni   = (e1 - s1) + (e2 - s2) - inter;
    return inter / fmaxf(uni, 1e-6f);
}

__global__ void __launch_bounds__(512, 1)
head_kernel(const float* __restrict__ sw, const float* __restrict__ sb,
            const float* __restrict__ dw, const float* __restrict__ db,
            const float* __restrict__ gt, const int* __restrict__ vlen,
            float* __restrict__ out) {
    __shared__ float s_sl[16 * 64], s_dl[16 * 64];
    __shared__ float s_bs[NANCH], s_be[NANCH], s_sc[NANCH];
    __shared__ float s_as[NANCH], s_ae[NANCH];
    __shared__ float s_lp0[NANCH], s_lp1[NANCH], s_dc[NANCH], s_dt[NANCH];
    __shared__ float s_gt[16];
    __shared__ int   s_best[8];
    __shared__ float r0[512], r1[512], r2[512], r3[512];

    const int tid  = threadIdx.x;
    const int wid  = tid >> 5;
    const int lane = tid & 31;
    if (tid < 16) s_gt[tid] = gt[tid];

    const int o = tid >> 6;
    const int t = tid & 63;
    {
        float a0 = sb[o], a1 = sb[o + 8], d0 = db[o], d1 = db[o + 8];
        for (int c = 0; c < C2; c++) {
            float f = g_feat[c * 64 + t];
            a0 = fmaf(sw[o * 512 + c],       f, a0);
            a1 = fmaf(sw[(o + 8) * 512 + c], f, a1);
            d0 = fmaf(dw[o * 512 + c],       f, d0);
            d1 = fmaf(dw[(o + 8) * 512 + c], f, d1);
        }
        s_sl[o * 64 + t] = a0;  s_sl[(o + 8) * 64 + t] = a1;
        s_dl[o * 64 + t] = d0;  s_dl[(o + 8) * 64 + t] = d1;
    }
    __syncthreads();

    {
        const int a = o;
        float l0 = s_sl[a * 64 + t], l1 = s_sl[(a + 8) * 64 + t];
        float mx = fmaxf(l0, l1);
        float lse = mx + logf(expf(l0 - mx) + expf(l1 - mx));
        float p1  = expf(l1 - lse);
        float dc  = s_dl[a * 64 + t], dl = s_dl[(a + 8) * 64 + t];
        float alen = (float)(8 << a);
        float ctr  = (t + 0.5f) * 8.f;
        float pc = ctr + dc * alen;
        float pl = alen * expf(fminf(fmaxf(dl, -10.f), 10.f));
        float ps = fminf(fmaxf(pc - 0.5f * pl, 0.f), 512.f);
        float pe = fminf(fmaxf(pc + 0.5f * pl, 0.f), 512.f);
        s_bs[tid] = ps;  s_be[tid] = pe;
        s_sc[tid] = (pe - ps >= 4.f) ? p1 : -1.0e9f;
        s_as[tid] = ctr - 0.5f * alen;
        s_ae[tid] = ctr + 0.5f * alen;
        s_lp0[tid] = l0 - lse;  s_lp1[tid] = l1 - lse;
        s_dc[tid] = dc;  s_dt[tid] = dl;
    }
    __syncthreads();

    if (wid < 8) {
        float gs = s_gt[wid * 2], ge = s_gt[wid * 2 + 1];
        float bv = -3.4e38f; int bi = 0x7fffffff;
        for (int k = 0; k < 16; k++) {
            int n = lane + 32 * k;
            float v = iou1d(s_as[n], s_ae[n], gs, ge);
            if (v > bv) { bv = v; bi = n; }
        }
        for (int off = 16; off; off >>= 1) {
            float ov = __shfl_xor_sync(0xffffffffu, bv, off);
            int   oi = __shfl_xor_sync(0xffffffffu, bi, off);
            if (ov > bv || (ov == bv && oi < bi)) { bv = ov; bi = oi; }
        }
        if (lane == 0) s_best[wid] = bi;
    }
    __syncthreads();

    {
        float myas = s_as[tid], myae = s_ae[tid];
        float miou = -1.f; int ag = 0;
#pragma unroll
        for (int g = 0; g < 8; g++) {
            float v = iou1d(myas, myae, s_gt[2 * g], s_gt[2 * g + 1]);
            if (v > miou) { miou = v; ag = g; }
        }
        int lab = (miou < 0.3f) ? 0 : -1;
        if (miou >= 0.7f) lab = 1;
#pragma unroll
        for (int g = 0; g < 8; g++)
            if (s_best[g] == tid) lab = 1;
        float vl = (float)vlen[0];
        if (!(myas >= 0.f && myae <= vl)) lab = -1;

        float gs = s_gt[2 * ag], ge = s_gt[2 * ag + 1];
        float gc = 0.5f * (gs + ge);
        float gl = fmaxf(ge - gs, 1e-6f);
        float ac = 0.5f * (myas + myae);
        float al = myae - myas;
        float rl0 = (gc - ac) / al;
        float rl1 = logf(gl / al);
        float d0 = s_dc[tid] - rl0, d1 = s_dt[tid] - rl1;
        float sl1 = (fabsf(d0) < 1.f ? 0.5f * d0 * d0 : fabsf(d0) - 0.5f)
                  + (fabsf(d1) < 1.f ? 0.5f * d1 * d1 : fabsf(d1) - 0.5f);
        float maskv = (lab >= 0) ? 1.f : 0.f;
        float posv  = (lab == 1) ? 1.f : 0.f;
        float nll   = -((lab == 1) ? s_lp1[tid] : s_lp0[tid]);
        r0[tid] = nll * maskv;  r1[tid] = maskv;
        r2[tid] = sl1 * posv;   r3[tid] = posv;
    }
    __syncthreads();
    for (int s = 256; s > 0; s >>= 1) {
        if (tid < s) {
            r0[tid] += r0[tid + s];  r1[tid] += r1[tid + s];
            r2[tid] += r2[tid + s];  r3[tid] += r3[tid + s];
        }
        __syncthreads();
    }
    if (tid == 0) {
        out[300] = r0[0] / fmaxf(r1[0], 1.f);
        out[301] = r2[0] / fmaxf(r3[0], 1.f);
    }
    __syncthreads();

    if (wid == 0) {
        for (int it = 0; it < 100; it++) {
            float bv = -3.4e38f; int bi = 0x7fffffff;
#pragma unroll
            for (int k = 0; k < 16; k++) {
                int n = lane + 32 * k;
                float v = s_sc[n];
                if (v > bv) { bv = v; bi = n; }
            }
            for (int off = 16; off; off >>= 1) {
                float ov = __shfl_xor_sync(0xffffffffu, bv, off);
                int   oi = __shfl_xor_sync(0xffffffffu, bi, off);
                if (ov > bv || (ov == bv && oi < bi)) { bv = ov; bi = oi; }
            }
            float kb0 = s_bs[bi], kb1 = s_be[bi];
            bool keep = bv > -5.0e8f;
            if (lane == 0) {
                out[2 * it]     = keep ? kb0 : 0.f;
                out[2 * it + 1] = keep ? kb1 : 0.f;
                out[200 + it]   = keep ? bv  : 0.f;
            }
#pragma unroll
            for (int k = 0; k < 16; k++) {
                int n = lane + 32 * k;
                float v = iou1d(kb0, kb1, s_bs[n], s_be[n]);
                if (v > 0.7f || n == bi) s_sc[n] = -1.0e9f;
            }
            __syncwarp();
        }
    }
}

// ============================================================================
extern "C" void kernel_launch(void* const* d_in, const int* in_sizes, int n_in,
                              void* d_out, int out_size) {
    const float* base = (const float*)d_in[0];
    const float* gt   = (const float*)d_in[1];
    const int*   vl   = (const int*)d_in[2];
    const float* c1w  = (const float*)d_in[3];
    const float* c1b  = (const float*)d_in[4];
    const float* c2w  = (const float*)d_in[5];
    const float* c2b  = (const float*)d_in[6];
    const float* sw   = (const float*)d_in[7];
    const float* sb   = (const float*)d_in[8];
    const float* dw   = (const float*)d_in[9];
    const float* db   = (const float*)d_in[10];
    float* out = (float*)d_out;

    static int attr_set = 0;
    if (!attr_set) {
        cudaFuncSetAttribute(conv1_mma,
                             cudaFuncAttributeMaxDynamicSharedMemorySize, C1MMA_SMEM);
        cudaFuncSetAttribute(conv2_mma,
                             cudaFuncAttributeMaxDynamicSharedMemorySize, C2MMA_SMEM);
        attr_set = 1;
    }

    void *p1h, *p1l, *p2h, *p2l;
    cudaGetSymbolAddress(&p1h, g_p1h);
    cudaGetSymbolAddress(&p1l, g_p1l);
    cudaGetSymbolAddress(&p2h, g_p2h);
    cudaGetSymbolAddress(&p2l, g_p2l);

    memzero<<<1024, 256>>>((uint4*)p1h, P1_ELEMS * 2 / 16);
    memzero<<<1024, 256>>>((uint4*)p1l, P1_ELEMS * 2 / 16);
    memzero<<<1024, 256>>>((uint4*)p2h, P2_ELEMS * 2 / 16);
    memzero<<<1024, 256>>>((uint4*)p2l, P2_ELEMS * 2 / 16);
    split_w1<<<512, 256>>>(c1w);
    split_w2<<<512, 256>>>(c2w);
    pad_split1<<<dim3(64, 32), 256>>>(base);
    conv1_mma<<<dim3(64, 4, 2), 128, C1MMA_SMEM>>>(c1b);
    conv2_mma<<<dim3(64, 2, 2), 128, C2MMA_SMEM>>>();
    reduce2<<<64, 512>>>(c2b);
    head_kernel<<<1, 512>>>(sw, sb, dw, db, gt, vl, out);
}

// round 15
// speedup vs baseline: 1.0430x; 1.0121x over previous
#include <cuda_runtime.h>
#include <cuda_bf16.h>
#include <cstdint>

typedef unsigned long long ull;

// ---------------- problem constants ----------------
#define CIN   256
#define TT    64
#define HIN   32
#define WIN   32
#define C1    512
#define C2    512
#define NANCH 512

// conv1 GEMM: K1 = 27 taps * 256 ic (tap-major: k = tap*256 + ic)
#define K1      6912
#define NCHUNK1 324            // 3 segments * 108 (27 tap * 4 icc)
#define STAGE1_BYTES 40960     // A 8KB + B 32KB
#define C1MMA_SMEM  (2 * STAGE1_BYTES)   // 80KB, 2 CTAs/SM

// conv2 GEMM: K2 = 27 taps * 512 ic (tap-major)
#define K2      13824
#define NCHUNK2 648            // 3 segments * 216 (27 tap * 8 icc)
#define STAGE2_BYTES 24576     // A 8KB + B 16KB
#define C2MMA_SMEM  (3 * STAGE2_BYTES)   // 72KB, 2 CTAs/SM

// padded activation tensors (ic innermost); halos NEVER written -> stay at
// CUDA static zero-init across all graph replays (no memzero needed).
#define P1_ELEMS ((size_t)66 * 34 * 34 * 256)
#define P2_ELEMS ((size_t)66 * 18 * 18 * 512)

// ---------------- device scratch ----------------
__device__ __align__(16) __nv_bfloat16 g_p1h[P1_ELEMS];          // 39 MB
__device__ __align__(16) __nv_bfloat16 g_p1l[P1_ELEMS];          // 39 MB
__device__ __align__(16) __nv_bfloat16 g_p2h[P2_ELEMS];          // 22 MB
__device__ __align__(16) __nv_bfloat16 g_p2l[P2_ELEMS];          // 22 MB
__device__ __align__(16) __nv_bfloat16 g_b1h[(size_t)C1 * K1];   //  7 MB
__device__ __align__(16) __nv_bfloat16 g_b1l[(size_t)C1 * K1];   //  7 MB
__device__ __align__(16) __nv_bfloat16 g_b2h[(size_t)C2 * K2];   // 14 MB
__device__ __align__(16) __nv_bfloat16 g_b2l[(size_t)C2 * K2];   // 14 MB
__device__ __align__(16) float g_feat[TT * C2];                  // [t][oc]

// ---------------- helpers ----------------
__device__ __forceinline__ void cp16u(unsigned dst, const void* src) {
    asm volatile("cp.async.cg.shared.global [%0], [%1], 16;" :: "r"(dst), "l"(src));
}
__device__ __forceinline__ uint32_t smem_u32(const void* p) {
    return (uint32_t)__cvta_generic_to_shared(p);
}
__device__ __forceinline__ unsigned pack_bf2(float a, float b) {
    __nv_bfloat162 p = __floats2bfloat162_rn(a, b);
    return *reinterpret_cast<unsigned*>(&p);
}

// ============================================================================
// split_w1: w1[oc][ic*27+tap] -> b1 [oc][tap*256+ic] hi/lo
// ============================================================================
__global__ void split_w1(const float* __restrict__ w) {
    int oc = blockIdx.x;
    const float* src = w + (size_t)oc * K1;
    __nv_bfloat16* dh = g_b1h + (size_t)oc * K1;
    __nv_bfloat16* dl = g_b1l + (size_t)oc * K1;
#pragma unroll 3
    for (int j = 0; j < 27; j++) {
        int k = threadIdx.x + j * 256;
        int tap = k >> 8, ic = k & 255;
        float v = src[ic * 27 + tap];
        __nv_bfloat16 hi = __float2bfloat16(v);
        dh[k] = hi;
        dl[k] = __float2bfloat16(v - __bfloat162float(hi));
    }
}

// ============================================================================
// split_w2: w2[oc][ic*27+tap] -> b2 [oc][tap*512+ic] hi/lo
// ============================================================================
__global__ void split_w2(const float* __restrict__ w) {
    int oc = blockIdx.x;
    const float* src = w + (size_t)oc * (512 * 27);
    __nv_bfloat16* dh = g_b2h + (size_t)oc * K2;
    __nv_bfloat16* dl = g_b2l + (size_t)oc * K2;
#pragma unroll 6
    for (int j = 0; j < 54; j++) {
        int k = threadIdx.x + j * 256;
        int tap = k >> 9, ic = k & 511;
        float v = src[ic * 27 + tap];
        __nv_bfloat16 hi = __float2bfloat16(v);
        dh[k] = hi;
        dl[k] = __float2bfloat16(v - __bfloat162float(hi));
    }
}

// ============================================================================
// pad_split1: input [ic][t][h][w] fp32 -> P1 [t+1][h+1][w+1][ic] hi/lo bf16
// ============================================================================
__global__ void __launch_bounds__(256)
pad_split1(const float* __restrict__ in) {
    __shared__ float sm[256 * 33];
    const int t = blockIdx.x;
    const int h = blockIdx.y;
    const int tid = threadIdx.x;

#pragma unroll 8
    for (int j = 0; j < 32; j++) {
        int k = tid + j * 256;
        int ic = k >> 5, w = k & 31;
        sm[ic * 33 + w] = in[((size_t)(ic * TT + t) * HIN + h) * WIN + w];
    }
    __syncthreads();

    const int w   = tid >> 3;
    const int icg = tid & 7;
    float v[32];
#pragma unroll
    for (int i = 0; i < 32; i++) {
        int jj = i ^ (icg << 2);
        v[jj] = sm[(icg * 32 + jj) * 33 + w];
    }
    unsigned uh[16], ul[16];
#pragma unroll
    for (int p = 0; p < 16; p++) {
        float a = v[2 * p], b = v[2 * p + 1];
        uh[p] = pack_bf2(a, b);
        float ah = __bfloat162float(__float2bfloat16(a));
        float bh = __bfloat162float(__float2bfloat16(b));
        ul[p] = pack_bf2(a - ah, b - bh);
    }
    const size_t row = (((size_t)(t + 1) * 34) + (h + 1)) * 34 + (w + 1);
    uint4* dh = (uint4*)(g_p1h + row * 256 + icg * 32);
    uint4* dl = (uint4*)(g_p1l + row * 256 + icg * 32);
    dh[0] = make_uint4(uh[0], uh[1], uh[2], uh[3]);
    dh[1] = make_uint4(uh[4], uh[5], uh[6], uh[7]);
    dh[2] = make_uint4(uh[8], uh[9], uh[10], uh[11]);
    dh[3] = make_uint4(uh[12], uh[13], uh[14], uh[15]);
    dl[0] = make_uint4(ul[0], ul[1], ul[2], ul[3]);
    dl[1] = make_uint4(ul[4], ul[5], ul[6], ul[7]);
    dl[2] = make_uint4(ul[8], ul[9], ul[10], ul[11]);
    dl[3] = make_uint4(ul[12], ul[13], ul[14], ul[15]);
}

// ============================================================================
// Conv1 via mma.sync bf16x3 GEMM, A gathered from P1 (no im2col).
// Grid (t=64, mq=4, nq=2). 128 thr = 4 warps (1m x 4n), warp tile 64x64.
// 2-stage pipeline, 2 CTAs/SM.  (exact R10 kernel)
// ============================================================================
__global__ void __launch_bounds__(128, 2)
conv1_mma(const float* __restrict__ bias) {
    extern __shared__ __align__(128) char dsmem[];

    const int t    = blockIdx.x;
    const int mq   = blockIdx.y;
    const int nq   = blockIdx.z;
    const int tid  = threadIdx.x;
    const int warp = tid >> 5;
    const int lane = tid & 31;
    const int wn   = warp;

    const uint32_t abase = smem_u32(dsmem);

    const int aRow = ((lane >> 3) & 1) * 8 + (lane & 7);
    const int kA   = lane >> 4;
    const int sA   = aRow & 7;
    const int bRow = wn * 64 + ((lane >> 4) << 3) + (lane & 7);
    const int kB   = (lane >> 3) & 1;
    const int sB   = bRow & 7;

    float acc[4][8][4];
#pragma unroll
    for (int mi = 0; mi < 4; mi++)
#pragma unroll
        for (int ni = 0; ni < 8; ni++)
#pragma unroll
            for (int r = 0; r < 4; r++) acc[mi][ni][r] = 0.f;

    const size_t boff = (size_t)(nq * 256) * K1;

#define STAGE_LOAD1(CH, S)                                                     \
    {                                                                          \
        int seg = (CH) / 108;                                                  \
        int r   = (CH) - seg * 108;                                            \
        int tap = r >> 2, icc = r & 3;                                         \
        int kd = tap / 9, rr = tap - kd * 9, kh = rr / 3, kw = rr - kh * 3;    \
        const __nv_bfloat16* asrc = (seg == 1) ? g_p1l : g_p1h;                \
        const __nv_bfloat16* bsrc = (seg == 2) ? g_b1l : g_b1h;                \
        const size_t tb = (size_t)(t + kd) * (34 * 34 * 256) + icc * 64;       \
        uint32_t ab = abase + (S) * STAGE1_BYTES;                              \
        uint32_t bb = ab + 8192;                                               \
        _Pragma("unroll")                                                      \
        for (int j = 0; j < 4; j++) {                                          \
            int idx = tid + j * 128;                                           \
            int m = idx >> 3, kp = idx & 7;                                    \
            int mg = mq * 64 + m;                                              \
            int hp = 2 * (mg >> 4) + kh, wp = 2 * (mg & 15) + kw;              \
            cp16u(ab + m * 128 + ((kp ^ (m & 7)) << 4),                        \
                  asrc + tb + ((size_t)hp * 34 + wp) * 256 + kp * 8);          \
        }                                                                      \
        _Pragma("unroll")                                                      \
        for (int j = 0; j < 16; j++) {                                         \
            int idx = tid + j * 128;                                           \
            int oc = idx >> 3, kp = idx & 7;                                   \
            cp16u(bb + oc * 128 + ((kp ^ (oc & 7)) << 4),                      \
                  bsrc + boff + (size_t)oc * K1 + r * 64 + kp * 8);            \
        }                                                                      \
    }

    STAGE_LOAD1(0, 0);
    asm volatile("cp.async.commit_group;");

    for (int c = 0; c < NCHUNK1; c++) {
        if (c + 1 < NCHUNK1) {
            STAGE_LOAD1(c + 1, (c + 1) & 1);
            asm volatile("cp.async.commit_group;");
            asm volatile("cp.async.wait_group 1;");
        } else {
            asm volatile("cp.async.wait_group 0;");
        }
        __syncthreads();

        const uint32_t abuf = abase + (c & 1) * STAGE1_BYTES;
        const uint32_t aB = abuf + aRow * 128;
        const uint32_t bB = abuf + 8192 + bRow * 128;

#pragma unroll
        for (int ks = 0; ks < 4; ks++) {
            uint32_t a[4][4];
#pragma unroll
            for (int mi = 0; mi < 4; mi++) {
                uint32_t ad = aB + mi * 2048 + (((2 * ks + kA) ^ sA) << 4);
                asm volatile(
                    "ldmatrix.sync.aligned.m8n8.x4.shared.b16 {%0,%1,%2,%3}, [%4];"
                    : "=r"(a[mi][0]), "=r"(a[mi][1]), "=r"(a[mi][2]), "=r"(a[mi][3])
                    : "r"(ad));
            }
            uint32_t bg[8][2];
#pragma unroll
            for (int p = 0; p < 4; p++) {
                uint32_t bd = bB + p * 2048 + (((2 * ks + kB) ^ sB) << 4);
                asm volatile(
                    "ldmatrix.sync.aligned.m8n8.x4.shared.b16 {%0,%1,%2,%3}, [%4];"
                    : "=r"(bg[2 * p][0]), "=r"(bg[2 * p][1]),
                      "=r"(bg[2 * p + 1][0]), "=r"(bg[2 * p + 1][1])
                    : "r"(bd));
            }
#pragma unroll
            for (int mi = 0; mi < 4; mi++)
#pragma unroll
                for (int ni = 0; ni < 8; ni++)
                    asm volatile(
                        "mma.sync.aligned.m16n8k16.row.col.f32.bf16.bf16.f32 "
                        "{%0,%1,%2,%3}, {%4,%5,%6,%7}, {%8,%9}, {%0,%1,%2,%3};"
                        : "+f"(acc[mi][ni][0]), "+f"(acc[mi][ni][1]),
                          "+f"(acc[mi][ni][2]), "+f"(acc[mi][ni][3])
                        : "r"(a[mi][0]), "r"(a[mi][1]), "r"(a[mi][2]), "r"(a[mi][3]),
                          "r"(bg[ni][0]), "r"(bg[ni][1]));
        }
        __syncthreads();
    }
#undef STAGE_LOAD1

    // epilogue: bias + hi/lo bf16 -> P2 [t+1][h1+1][w1+1][oc]
    const int mbase = mq * 64 + (lane >> 2);
    const int ncb   = nq * 256 + wn * 64 + 2 * (lane & 3);
#pragma unroll
    for (int mi = 0; mi < 4; mi++) {
        int m0 = mbase + mi * 16;
        int m1 = m0 + 8;
        size_t row0 = (((size_t)(t + 1) * 18) + ((m0 >> 4) + 1)) * 18 + ((m0 & 15) + 1);
        size_t row1 = (((size_t)(t + 1) * 18) + ((m1 >> 4) + 1)) * 18 + ((m1 & 15) + 1);
#pragma unroll
        for (int ni = 0; ni < 8; ni++) {
            int n0 = ncb + ni * 8;
            float b0 = bias[n0], b1 = bias[n0 + 1];
            float v00 = acc[mi][ni][0] + b0, v01 = acc[mi][ni][1] + b1;
            float v10 = acc[mi][ni][2] + b0, v11 = acc[mi][ni][3] + b1;
            unsigned h0 = pack_bf2(v00, v01), h1 = pack_bf2(v10, v11);
            float r00 = v00 - __bfloat162float(__float2bfloat16(v00));
            float r01 = v01 - __bfloat162float(__float2bfloat16(v01));
            float r10 = v10 - __bfloat162float(__float2bfloat16(v10));
            float r11 = v11 - __bfloat162float(__float2bfloat16(v11));
            *(unsigned*)(g_p2h + row0 * 512 + n0) = h0;
            *(unsigned*)(g_p2h + row1 * 512 + n0) = h1;
            *(unsigned*)(g_p2l + row0 * 512 + n0) = pack_bf2(r00, r01);
            *(unsigned*)(g_p2l + row1 * 512 + n0) = pack_bf2(r10, r11);
        }
    }
}

// ============================================================================
// Conv2 via mma.sync bf16x3 GEMM + fused maxpool (exact R10 kernel,
// g_feat transposed to [t][oc]). Grid (t=64, nq=4). 128 thr = 4 warps,
// warp tile 64x32, 3-stage, 2 CTAs/SM.
// ============================================================================
__global__ void __launch_bounds__(128, 2)
conv2_mma(const float* __restrict__ bias) {
    extern __shared__ __align__(128) char dsmem[];

    const int t    = blockIdx.x;
    const int nq   = blockIdx.y;
    const int tid  = threadIdx.x;
    const int warp = tid >> 5;
    const int lane = tid & 31;
    const int wn   = warp;

    const uint32_t abase = smem_u32(dsmem);

    const int aRow = ((lane >> 3) & 1) * 8 + (lane & 7);
    const int kA   = lane >> 4;
    const int sA   = aRow & 7;
    const int bRow = wn * 32 + ((lane >> 4) << 3) + (lane & 7);
    const int kB   = (lane >> 3) & 1;
    const int sB   = bRow & 7;

    float acc[4][4][4];
#pragma unroll
    for (int mi = 0; mi < 4; mi++)
#pragma unroll
        for (int ni = 0; ni < 4; ni++)
#pragma unroll
            for (int r = 0; r < 4; r++) acc[mi][ni][r] = 0.f;

    const size_t boff = (size_t)(nq * 128) * K2;

#define STAGE_LOAD2(CH, S)                                                     \
    {                                                                          \
        int seg = (CH) / 216;                                                  \
        int r   = (CH) - seg * 216;                                            \
        int tap = r >> 3, icc = r & 7;                                         \
        int kd = tap / 9, rr = tap - kd * 9, kh = rr / 3, kw = rr - kh * 3;    \
        const __nv_bfloat16* asrc = (seg == 1) ? g_p2l : g_p2h;                \
        const __nv_bfloat16* bsrc = (seg == 2) ? g_b2l : g_b2h;                \
        const size_t tb = (size_t)(t + kd) * (18 * 18 * 512) + icc * 64;       \
        uint32_t ab = abase + (S) * STAGE2_BYTES;                              \
        uint32_t bb = ab + 8192;                                               \
        _Pragma("unroll")                                                      \
        for (int j = 0; j < 4; j++) {                                          \
            int idx = tid + j * 128;                                           \
            int m = idx >> 3, kp = idx & 7;                                    \
            int hp = 2 * (m >> 3) + kh, wp = 2 * (m & 7) + kw;                 \
            cp16u(ab + m * 128 + ((kp ^ (m & 7)) << 4),                        \
                  asrc + tb + ((size_t)hp * 18 + wp) * 512 + kp * 8);          \
        }                                                                      \
        _Pragma("unroll")                                                      \
        for (int j = 0; j < 8; j++) {                                          \
            int idx = tid + j * 128;                                           \
            int oc = idx >> 3, kp = idx & 7;                                   \
            cp16u(bb + oc * 128 + ((kp ^ (oc & 7)) << 4),                      \
                  bsrc + boff + (size_t)oc * K2 + r * 64 + kp * 8);            \
        }                                                                      \
    }

    STAGE_LOAD2(0, 0);
    asm volatile("cp.async.commit_group;");
    STAGE_LOAD2(1, 1);
    asm volatile("cp.async.commit_group;");

    int sc = 0;
    for (int c = 0; c < NCHUNK2; c++) {
        if (c + 1 < NCHUNK2) asm volatile("cp.async.wait_group 1;");
        else                 asm volatile("cp.async.wait_group 0;");
        __syncthreads();
        if (c + 2 < NCHUNK2) {
            int sn = sc + 2; if (sn >= 3) sn -= 3;
            STAGE_LOAD2(c + 2, sn);
            asm volatile("cp.async.commit_group;");
        }

        const uint32_t abuf = abase + sc * STAGE2_BYTES;
        const uint32_t aB = abuf + aRow * 128;
        const uint32_t bB = abuf + 8192 + bRow * 128;

#pragma unroll
        for (int ks = 0; ks < 4; ks++) {
            uint32_t a[4][4];
#pragma unroll
            for (int mi = 0; mi < 4; mi++) {
                uint32_t ad = aB + mi * 2048 + (((2 * ks + kA) ^ sA) << 4);
                asm volatile(
                    "ldmatrix.sync.aligned.m8n8.x4.shared.b16 {%0,%1,%2,%3}, [%4];"
                    : "=r"(a[mi][0]), "=r"(a[mi][1]), "=r"(a[mi][2]), "=r"(a[mi][3])
                    : "r"(ad));
            }
            uint32_t bg[4][2];
#pragma unroll
            for (int p = 0; p < 2; p++) {
                uint32_t bd = bB + p * 2048 + (((2 * ks + kB) ^ sB) << 4);
                asm volatile(
                    "ldmatrix.sync.aligned.m8n8.x4.shared.b16 {%0,%1,%2,%3}, [%4];"
                    : "=r"(bg[2 * p][0]), "=r"(bg[2 * p][1]),
                      "=r"(bg[2 * p + 1][0]), "=r"(bg[2 * p + 1][1])
                    : "r"(bd));
            }
#pragma unroll
            for (int mi = 0; mi < 4; mi++)
#pragma unroll
                for (int ni = 0; ni < 4; ni++)
                    asm volatile(
                        "mma.sync.aligned.m16n8k16.row.col.f32.bf16.bf16.f32 "
                        "{%0,%1,%2,%3}, {%4,%5,%6,%7}, {%8,%9}, {%0,%1,%2,%3};"
                        : "+f"(acc[mi][ni][0]), "+f"(acc[mi][ni][1]),
                          "+f"(acc[mi][ni][2]), "+f"(acc[mi][ni][3])
                        : "r"(a[mi][0]), "r"(a[mi][1]), "r"(a[mi][2]), "r"(a[mi][3]),
                          "r"(bg[ni][0]), "r"(bg[ni][1]));
        }
        __syncthreads();
        if (++sc == 3) sc = 0;
    }
#undef STAGE_LOAD2

    // fused maxpool epilogue -> g_feat[t][oc]
#pragma unroll
    for (int ni = 0; ni < 4; ni++) {
        float me = -3.4e38f, mo = -3.4e38f;
#pragma unroll
        for (int mi = 0; mi < 4; mi++) {
            me = fmaxf(me, fmaxf(acc[mi][ni][0], acc[mi][ni][2]));
            mo = fmaxf(mo, fmaxf(acc[mi][ni][1], acc[mi][ni][3]));
        }
#pragma unroll
        for (int off = 4; off < 32; off <<= 1) {
            me = fmaxf(me, __shfl_xor_sync(0xffffffffu, me, off));
            mo = fmaxf(mo, __shfl_xor_sync(0xffffffffu, mo, off));
        }
        if (lane < 4) {
            int oc = nq * 128 + wn * 32 + ni * 8 + 2 * lane;
            g_feat[t * 512 + oc]     = me + bias[oc];
            g_feat[t * 512 + oc + 1] = mo + bias[oc + 1];
        }
    }
}

// ============================================================================
// Head: vectorized phase-A GEMM (float4 over c), rest unchanged from R1.
// ============================================================================
__device__ __forceinline__ float iou1d(float s1, float e1, float s2, float e2) {
    float inter = fmaxf(fminf(e1, e2) - fmaxf(s1, s2), 0.f);
    float uni   = (e1 - s1) + (e2 - s2) - inter;
    return inter / fmaxf(uni, 1e-6f);
}

__global__ void __launch_bounds__(512, 1)
head_kernel(const float* __restrict__ sw, const float* __restrict__ sb,
            const float* __restrict__ dw, const float* __restrict__ db,
            const float* __restrict__ gt, const int* __restrict__ vlen,
            float* __restrict__ out) {
    __shared__ float s_sl[16 * 64], s_dl[16 * 64];
    __shared__ float s_bs[NANCH], s_be[NANCH], s_sc[NANCH];
    __shared__ float s_as[NANCH], s_ae[NANCH];
    __shared__ float s_lp0[NANCH], s_lp1[NANCH], s_dc[NANCH], s_dt[NANCH];
    __shared__ float s_gt[16];
    __shared__ int   s_best[8];
    __shared__ float r0[512], r1[512], r2[512], r3[512];

    const int tid  = threadIdx.x;
    const int wid  = tid >> 5;
    const int lane = tid & 31;
    if (tid < 16) s_gt[tid] = gt[tid];

    const int o = tid >> 6;
    const int t = tid & 63;
    {
        float a0 = sb[o], a1 = sb[o + 8], d0 = db[o], d1 = db[o + 8];
        const float4* fp = (const float4*)(g_feat + t * 512);
        const float4* s0 = (const float4*)(sw + o * 512);
        const float4* s1 = (const float4*)(sw + (o + 8) * 512);
        const float4* w0 = (const float4*)(dw + o * 512);
        const float4* w1 = (const float4*)(dw + (o + 8) * 512);
        for (int c4 = 0; c4 < 128; c4++) {
            float4 f  = fp[c4];
            float4 x0 = s0[c4], x1 = s1[c4], y0 = w0[c4], y1 = w1[c4];
            a0 = fmaf(x0.x, f.x, a0); a0 = fmaf(x0.y, f.y, a0);
            a0 = fmaf(x0.z, f.z, a0); a0 = fmaf(x0.w, f.w, a0);
            a1 = fmaf(x1.x, f.x, a1); a1 = fmaf(x1.y, f.y, a1);
            a1 = fmaf(x1.z, f.z, a1); a1 = fmaf(x1.w, f.w, a1);
            d0 = fmaf(y0.x, f.x, d0); d0 = fmaf(y0.y, f.y, d0);
            d0 = fmaf(y0.z, f.z, d0); d0 = fmaf(y0.w, f.w, d0);
            d1 = fmaf(y1.x, f.x, d1); d1 = fmaf(y1.y, f.y, d1);
            d1 = fmaf(y1.z, f.z, d1); d1 = fmaf(y1.w, f.w, d1);
        }
        s_sl[o * 64 + t] = a0;  s_sl[(o + 8) * 64 + t] = a1;
        s_dl[o * 64 + t] = d0;  s_dl[(o + 8) * 64 + t] = d1;
    }
    __syncthreads();

    {
        const int a = o;
        float l0 = s_sl[a * 64 + t], l1 = s_sl[(a + 8) * 64 + t];
        float mx = fmaxf(l0, l1);
        float lse = mx + logf(expf(l0 - mx) + expf(l1 - mx));
        float p1  = expf(l1 - lse);
        float dc  = s_dl[a * 64 + t], dl = s_dl[(a + 8) * 64 + t];
        float alen = (float)(8 << a);
        float ctr  = (t + 0.5f) * 8.f;
        float pc = ctr + dc * alen;
        float pl = alen * expf(fminf(fmaxf(dl, -10.f), 10.f));
        float ps = fminf(fmaxf(pc - 0.5f * pl, 0.f), 512.f);
        float pe = fminf(fmaxf(pc + 0.5f * pl, 0.f), 512.f);
        s_bs[tid] = ps;  s_be[tid] = pe;
        s_sc[tid] = (pe - ps >= 4.f) ? p1 : -1.0e9f;
        s_as[tid] = ctr - 0.5f * alen;
        s_ae[tid] = ctr + 0.5f * alen;
        s_lp0[tid] = l0 - lse;  s_lp1[tid] = l1 - lse;
        s_dc[tid] = dc;  s_dt[tid] = dl;
    }
    __syncthreads();

    if (wid < 8) {
        float gs = s_gt[wid * 2], ge = s_gt[wid * 2 + 1];
        float bv = -3.4e38f; int bi = 0x7fffffff;
        for (int k = 0; k < 16; k++) {
            int n = lane + 32 * k;
            float v = iou1d(s_as[n], s_ae[n], gs, ge);
            if (v > bv) { bv = v; bi = n; }
        }
        for (int off = 16; off; off >>= 1) {
            float ov = __shfl_xor_sync(0xffffffffu, bv, off);
            int   oi = __shfl_xor_sync(0xffffffffu, bi, off);
            if (ov > bv || (ov == bv && oi < bi)) { bv = ov; bi = oi; }
        }
        if (lane == 0) s_best[wid] = bi;
    }
    __syncthreads();

    {
        float myas = s_as[tid], myae = s_ae[tid];
        float miou = -1.f; int ag = 0;
#pragma unroll
        for (int g = 0; g < 8; g++) {
            float v = iou1d(myas, myae, s_gt[2 * g], s_gt[2 * g + 1]);
            if (v > miou) { miou = v; ag = g; }
        }
        int lab = (miou < 0.3f) ? 0 : -1;
        if (miou >= 0.7f) lab = 1;
#pragma unroll
        for (int g = 0; g < 8; g++)
            if (s_best[g] == tid) lab = 1;
        float vl = (float)vlen[0];
        if (!(myas >= 0.f && myae <= vl)) lab = -1;

        float gs = s_gt[2 * ag], ge = s_gt[2 * ag + 1];
        float gc = 0.5f * (gs + ge);
        float gl = fmaxf(ge - gs, 1e-6f);
        float ac = 0.5f * (myas + myae);
        float al = myae - myas;
        float rl0 = (gc - ac) / al;
        float rl1 = logf(gl / al);
        float d0 = s_dc[tid] - rl0, d1 = s_dt[tid] - rl1;
        float sl1 = (fabsf(d0) < 1.f ? 0.5f * d0 * d0 : fabsf(d0) - 0.5f)
                  + (fabsf(d1) < 1.f ? 0.5f * d1 * d1 : fabsf(d1) - 0.5f);
        float maskv = (lab >= 0) ? 1.f : 0.f;
        float posv  = (lab == 1) ? 1.f : 0.f;
        float nll   = -((lab == 1) ? s_lp1[tid] : s_lp0[tid]);
        r0[tid] = nll * maskv;  r1[tid] = maskv;
        r2[tid] = sl1 * posv;   r3[tid] = posv;
    }
    __syncthreads();
    for (int s = 256; s > 0; s >>= 1) {
        if (tid < s) {
            r0[tid] += r0[tid + s];  r1[tid] += r1[tid + s];
            r2[tid] += r2[tid + s];  r3[tid] += r3[tid + s];
        }
        __syncthreads();
    }
    if (tid == 0) {
        out[300] = r0[0] / fmaxf(r1[0], 1.f);
        out[301] = r2[0] / fmaxf(r3[0], 1.f);
    }
    __syncthreads();

    if (wid == 0) {
        for (int it = 0; it < 100; it++) {
            float bv = -3.4e38f; int bi = 0x7fffffff;
#pragma unroll
            for (int k = 0; k < 16; k++) {
                int n = lane + 32 * k;
                float v = s_sc[n];
                if (v > bv) { bv = v; bi = n; }
            }
            for (int off = 16; off; off >>= 1) {
                float ov = __shfl_xor_sync(0xffffffffu, bv, off);
                int   oi = __shfl_xor_sync(0xffffffffu, bi, off);
                if (ov > bv || (ov == bv && oi < bi)) { bv = ov; bi = oi; }
            }
            float kb0 = s_bs[bi], kb1 = s_be[bi];
            bool keep = bv > -5.0e8f;
            if (lane == 0) {
                out[2 * it]     = keep ? kb0 : 0.f;
                out[2 * it + 1] = keep ? kb1 : 0.f;
                out[200 + it]   = keep ? bv  : 0.f;
            }
#pragma unroll
            for (int k = 0; k < 16; k++) {
                int n = lane + 32 * k;
                float v = iou1d(kb0, kb1, s_bs[n], s_be[n]);
                if (v > 0.7f || n == bi) s_sc[n] = -1.0e9f;
            }
            __syncwarp();
        }
    }
}

// ============================================================================
extern "C" void kernel_launch(void* const* d_in, const int* in_sizes, int n_in,
                              void* d_out, int out_size) {
    const float* base = (const float*)d_in[0];
    const float* gt   = (const float*)d_in[1];
    const int*   vl   = (const int*)d_in[2];
    const float* c1w  = (const float*)d_in[3];
    const float* c1b  = (const float*)d_in[4];
    const float* c2w  = (const float*)d_in[5];
    const float* c2b  = (const float*)d_in[6];
    const float* sw   = (const float*)d_in[7];
    const float* sb   = (const float*)d_in[8];
    const float* dw   = (const float*)d_in[9];
    const float* db   = (const float*)d_in[10];
    float* out = (float*)d_out;

    static int attr_set = 0;
    if (!attr_set) {
        cudaFuncSetAttribute(conv1_mma,
                             cudaFuncAttributeMaxDynamicSharedMemorySize, C1MMA_SMEM);
        cudaFuncSetAttribute(conv2_mma,
                             cudaFuncAttributeMaxDynamicSharedMemorySize, C2MMA_SMEM);
        attr_set = 1;
    }

    split_w1<<<512, 256>>>(c1w);
    split_w2<<<512, 256>>>(c2w);
    pad_split1<<<dim3(64, 32), 256>>>(base);
    conv1_mma<<<dim3(64, 4, 2), 128, C1MMA_SMEM>>>(c1b);
    conv2_mma<<<dim3(64, 4), 128, C2MMA_SMEM>>>(c2b);
    head_kernel<<<1, 512>>>(sw, sb, dw, db, gt, vl, out);
}